// round 1
// baseline (speedup 1.0000x reference)
#include <cuda_runtime.h>
#include <math.h>

// Problem constants
#define HDIM 768
#define DDIM 128
#define BATCH 64
#define SQ 128
#define SD 1024
#define NTOK_Q (BATCH * SQ)   // 8192
#define NTOK_D (BATCH * SD)   // 65536
#define NJCHUNK 8             // SD / 128

// Scratch (device globals: allocation-free per harness rules)
__device__ float g_q_emb[NTOK_Q * DDIM];            // 4 MB
__device__ float g_d_emb[(size_t)NTOK_D * DDIM];    // 32 MB
__device__ float g_pmax[BATCH * NJCHUNK * SQ];      // 256 KB

// ---------------------------------------------------------------------------
// Kernel 1: projection + L2 normalize.
//   E[t, :] = normalize( (X[t,:] * mask[t]) @ W^T )
// X: [numTokens, HDIM] row-major, W: [DDIM, HDIM] row-major.
// One block computes a 128-token x 128-dim output tile (DDIM == 128 so a block
// owns complete rows -> can normalize in-register with shuffle reductions).
// 256 threads, 8x8 micro-tile per thread with split-4 register mapping:
//   rows:  {ty*4 + r, 64 + ty*4 + r},  cols: {tx*4 + c, 64 + tx*4 + c}
// ---------------------------------------------------------------------------
#define KC1 16
#define LDA 132   // padded smem leading dim (keeps 16B alignment, reduces conflicts)

__global__ __launch_bounds__(256) void proj_kernel(
    const float* __restrict__ X,
    const int*   __restrict__ mask,
    const float* __restrict__ W,
    float*       __restrict__ E)
{
    __shared__ float As[KC1][LDA];
    __shared__ float Bs[KC1][LDA];

    const int tid = threadIdx.x;
    const int ty = tid >> 4;      // 0..15
    const int tx = tid & 15;      // 0..15
    const int row0 = blockIdx.x * 128;

    float acc[8][8];
#pragma unroll
    for (int r = 0; r < 8; r++)
#pragma unroll
        for (int c = 0; c < 8; c++) acc[r][c] = 0.f;

    for (int k0 = 0; k0 < HDIM; k0 += KC1) {
        __syncthreads();
        // Load A (X tile, mask applied) and B (W tile), both transposed to [k][row].
        // 128 rows x 16 k = 512 float4; 2 per thread.
#pragma unroll
        for (int i = 0; i < 2; i++) {
            int f = tid + i * 256;        // [0, 512)
            int row = f >> 2;             // [0, 128)
            int kq = (f & 3) * 4;         // {0,4,8,12}
            float4 a = *(const float4*)&X[(size_t)(row0 + row) * HDIM + k0 + kq];
            float mv = (float)mask[row0 + row];
            As[kq + 0][row] = a.x * mv;
            As[kq + 1][row] = a.y * mv;
            As[kq + 2][row] = a.z * mv;
            As[kq + 3][row] = a.w * mv;
            float4 b = *(const float4*)&W[(size_t)row * HDIM + k0 + kq];
            Bs[kq + 0][row] = b.x;
            Bs[kq + 1][row] = b.y;
            Bs[kq + 2][row] = b.z;
            Bs[kq + 3][row] = b.w;
        }
        __syncthreads();

#pragma unroll
        for (int kk = 0; kk < KC1; kk++) {
            float a[8], b[8];
            *(float4*)&a[0] = *(const float4*)&As[kk][ty * 4];
            *(float4*)&a[4] = *(const float4*)&As[kk][64 + ty * 4];
            *(float4*)&b[0] = *(const float4*)&Bs[kk][tx * 4];
            *(float4*)&b[4] = *(const float4*)&Bs[kk][64 + tx * 4];
#pragma unroll
            for (int r = 0; r < 8; r++)
#pragma unroll
                for (int c = 0; c < 8; c++) acc[r][c] += a[r] * b[c];
        }
    }

    // Per-row L2 normalize. Threads sharing a ty group (16 consecutive tids,
    // i.e. a half-warp) jointly own each row's 128 columns.
#pragma unroll
    for (int r = 0; r < 8; r++) {
        float ss = 0.f;
#pragma unroll
        for (int c = 0; c < 8; c++) ss += acc[r][c] * acc[r][c];
#pragma unroll
        for (int o = 1; o < 16; o <<= 1)
            ss += __shfl_xor_sync(0xffffffffu, ss, o, 16);
        float scale = 1.0f / fmaxf(sqrtf(ss), 1e-12f);
        int m = (r < 4) ? (ty * 4 + r) : (64 + ty * 4 + (r - 4));
        float4 v0, v1;
        v0.x = acc[r][0] * scale; v0.y = acc[r][1] * scale;
        v0.z = acc[r][2] * scale; v0.w = acc[r][3] * scale;
        v1.x = acc[r][4] * scale; v1.y = acc[r][5] * scale;
        v1.z = acc[r][6] * scale; v1.w = acc[r][7] * scale;
        *(float4*)&E[(size_t)(row0 + m) * DDIM + tx * 4] = v0;
        *(float4*)&E[(size_t)(row0 + m) * DDIM + 64 + tx * 4] = v1;
    }
}

// ---------------------------------------------------------------------------
// Kernel 2: per-batch similarity + partial max over a 128-doc chunk.
// Block (b, jc): sim tile [128 q-tokens x 128 docs], K = 128.
// Writes g_pmax[(b*NJCHUNK + jc)*SQ + i] = max_j sim[i, j] over this chunk.
// ---------------------------------------------------------------------------
#define KC2 32

__global__ __launch_bounds__(256) void maxsim_kernel()
{
    __shared__ float Qs[KC2][LDA];
    __shared__ float Ds[KC2][LDA];

    const int b = blockIdx.x;
    const int jc = blockIdx.y;
    const float* __restrict__ q = g_q_emb + (size_t)b * SQ * DDIM;
    const float* __restrict__ d = g_d_emb + ((size_t)b * SD + (size_t)jc * 128) * DDIM;

    const int tid = threadIdx.x;
    const int ty = tid >> 4;
    const int tx = tid & 15;

    float acc[8][8];
#pragma unroll
    for (int r = 0; r < 8; r++)
#pragma unroll
        for (int c = 0; c < 8; c++) acc[r][c] = 0.f;

    for (int k0 = 0; k0 < DDIM; k0 += KC2) {
        __syncthreads();
        // 128 rows x 32 k = 1024 float4; 4 per thread. Transposed store.
#pragma unroll
        for (int i = 0; i < 4; i++) {
            int f = tid + i * 256;        // [0, 1024)
            int row = f >> 3;             // [0, 128)
            int kq = (f & 7) * 4;         // {0,4,...,28}
            float4 v = *(const float4*)&q[(size_t)row * DDIM + k0 + kq];
            Qs[kq + 0][row] = v.x; Qs[kq + 1][row] = v.y;
            Qs[kq + 2][row] = v.z; Qs[kq + 3][row] = v.w;
            float4 w = *(const float4*)&d[(size_t)row * DDIM + k0 + kq];
            Ds[kq + 0][row] = w.x; Ds[kq + 1][row] = w.y;
            Ds[kq + 2][row] = w.z; Ds[kq + 3][row] = w.w;
        }
        __syncthreads();

#pragma unroll
        for (int kk = 0; kk < KC2; kk++) {
            float a[8], bb[8];
            *(float4*)&a[0]  = *(const float4*)&Qs[kk][ty * 4];
            *(float4*)&a[4]  = *(const float4*)&Qs[kk][64 + ty * 4];
            *(float4*)&bb[0] = *(const float4*)&Ds[kk][tx * 4];
            *(float4*)&bb[4] = *(const float4*)&Ds[kk][64 + tx * 4];
#pragma unroll
            for (int r = 0; r < 8; r++)
#pragma unroll
                for (int c = 0; c < 8; c++) acc[r][c] += a[r] * bb[c];
        }
    }

    // Row-max over the 128 docs of this tile.
#pragma unroll
    for (int r = 0; r < 8; r++) {
        float m = acc[r][0];
#pragma unroll
        for (int c = 1; c < 8; c++) m = fmaxf(m, acc[r][c]);
#pragma unroll
        for (int o = 1; o < 16; o <<= 1)
            m = fmaxf(m, __shfl_xor_sync(0xffffffffu, m, o, 16));
        if (tx == 0) {
            int i = (r < 4) ? (ty * 4 + r) : (64 + ty * 4 + (r - 4));
            g_pmax[((size_t)b * NJCHUNK + jc) * SQ + i] = m;
        }
    }
}

// ---------------------------------------------------------------------------
// Kernel 3: finalize. out[b] = sum_i max_jc pmax[b, jc, i]
// ---------------------------------------------------------------------------
__global__ __launch_bounds__(128) void finalize_kernel(float* __restrict__ out)
{
    const int b = blockIdx.x;
    const int i = threadIdx.x;   // 0..127
    float m = g_pmax[((size_t)b * NJCHUNK + 0) * SQ + i];
#pragma unroll
    for (int jc = 1; jc < NJCHUNK; jc++)
        m = fmaxf(m, g_pmax[((size_t)b * NJCHUNK + jc) * SQ + i]);

    // sum over 128 threads
#pragma unroll
    for (int o = 16; o > 0; o >>= 1)
        m += __shfl_xor_sync(0xffffffffu, m, o, 32);
    __shared__ float s[4];
    if ((i & 31) == 0) s[i >> 5] = m;
    __syncthreads();
    if (i == 0) out[b] = s[0] + s[1] + s[2] + s[3];
}

// ---------------------------------------------------------------------------
extern "C" void kernel_launch(void* const* d_in, const int* in_sizes, int n_in,
                              void* d_out, int out_size)
{
    const float* qh = (const float*)d_in[0];   // [64,128,768]
    const int*   qm = (const int*)  d_in[1];   // [64,128]
    const float* dh = (const float*)d_in[2];   // [64,1024,768]
    const int*   dm = (const int*)  d_in[3];   // [64,1024]
    const float* W  = (const float*)d_in[4];   // [128,768]
    float* out = (float*)d_out;                // [64]

    float *gq = nullptr, *gd = nullptr;
    cudaGetSymbolAddress((void**)&gq, g_q_emb);
    cudaGetSymbolAddress((void**)&gd, g_d_emb);

    proj_kernel<<<NTOK_Q / 128, 256>>>(qh, qm, W, gq);
    proj_kernel<<<NTOK_D / 128, 256>>>(dh, dm, W, gd);
    maxsim_kernel<<<dim3(BATCH, NJCHUNK), 256>>>();
    finalize_kernel<<<BATCH, 128>>>(out);
}

// round 2
// speedup vs baseline: 2.4431x; 2.4431x over previous
#include <cuda_runtime.h>
#include <math.h>
#include <stdint.h>

// Problem constants
#define HDIM 768
#define DDIM 128
#define BATCH 64
#define SQ 128
#define SD 1024
#define NTOK_Q (BATCH * SQ)   // 8192
#define NTOK_D (BATCH * SD)   // 65536
#define NJCHUNK 8             // SD / 128
#define KC 16                 // K chunk
#define LDK 20                // smem leading dim (k) in words: conflict-free ldmatrix

// Scratch (device globals: allocation-free per harness rules)
__device__ float g_q_emb[NTOK_Q * DDIM];            // 4 MB
__device__ float g_d_emb[(size_t)NTOK_D * DDIM];    // 32 MB
__device__ float g_pmax[BATCH * NJCHUNK * SQ];      // 256 KB

// ---------------------------------------------------------------------------
// helpers
// ---------------------------------------------------------------------------
__device__ __forceinline__ uint32_t f2tf(float x) {
    uint32_t u; asm("cvt.rna.tf32.f32 %0, %1;" : "=r"(u) : "f"(x)); return u;
}
__device__ __forceinline__ float f2tff(float x) { return __uint_as_float(f2tf(x)); }

__device__ __forceinline__ void ldsm4(uint32_t& r0, uint32_t& r1, uint32_t& r2,
                                      uint32_t& r3, uint32_t addr) {
    asm volatile("ldmatrix.sync.aligned.m8n8.x4.shared.b16 {%0,%1,%2,%3}, [%4];"
                 : "=r"(r0), "=r"(r1), "=r"(r2), "=r"(r3) : "r"(addr));
}
__device__ __forceinline__ void mma8(float c[4], const uint32_t a[4], const uint32_t b[2]) {
    asm volatile("mma.sync.aligned.m16n8k8.row.col.f32.tf32.tf32.f32 "
                 "{%0,%1,%2,%3}, {%4,%5,%6,%7}, {%8,%9}, {%0,%1,%2,%3};"
                 : "+f"(c[0]), "+f"(c[1]), "+f"(c[2]), "+f"(c[3])
                 : "r"(a[0]), "r"(a[1]), "r"(a[2]), "r"(a[3]),
                   "r"(b[0]), "r"(b[1]));
}
__device__ __forceinline__ uint32_t s2u(const void* p) {
    return (uint32_t)__cvta_generic_to_shared(p);
}

// ---------------------------------------------------------------------------
// Kernel 1: projection + L2 normalize (tf32 tensor cores).
//   E[t,:] = normalize( (X[t,:] * mask[t]) @ W^T ),  X:[rows,768], W:[128,768]
// Block: 128 tokens x 128 dims. 8 warps in 4(m) x 2(n); warp tile 32x64.
// Double-buffered smem, K-chunks of 16.
// ---------------------------------------------------------------------------
__global__ __launch_bounds__(256) void proj_tf32(
    const float* __restrict__ X, const int* __restrict__ mask,
    const float* __restrict__ W, float* __restrict__ E)
{
    __shared__ float As[2][128][LDK];
    __shared__ float Bs[2][128][LDK];
    __shared__ float ssb[2][128];

    const int tid  = threadIdx.x;
    const int lane = tid & 31;
    const int warp = tid >> 5;
    const int warpM = (warp & 3) * 32;
    const int warpN = (warp >> 2) * 64;
    const int wn = warp >> 2;
    const int g = lane >> 2, tig = lane & 3;
    const int l7 = lane & 7, b3 = (lane >> 3) & 1, b4 = (lane >> 4) & 1;
    const int row0 = blockIdx.x * 128;

    // loader mapping: 512 float4 per tile side, 2 per thread
    const int lrow = tid >> 2;          // 0..63 (+64 for second)
    const int lkq  = (tid & 3) * 4;

    float acc[2][8][4];
#pragma unroll
    for (int i = 0; i < 2; i++)
#pragma unroll
        for (int j = 0; j < 8; j++)
#pragma unroll
            for (int e = 0; e < 4; e++) acc[i][j][e] = 0.f;

    // ldmatrix word offsets (add k8 + buffer offset later)
    uint32_t aOff[2], bOff[4];
#pragma unroll
    for (int i = 0; i < 2; i++)
        aOff[i] = (uint32_t)((warpM + i * 16 + l7 + b3 * 8) * LDK + b4 * 4);
#pragma unroll
    for (int jj = 0; jj < 4; jj++)
        bOff[jj] = (uint32_t)((warpN + jj * 16 + b4 * 8 + l7) * LDK + b3 * 4);

    const uint32_t aBase = s2u(&As[0][0][0]);
    const uint32_t bBase = s2u(&Bs[0][0][0]);
    const uint32_t bufB  = 128 * LDK * 4;   // bytes per buffer

    const float mv0 = (float)mask[row0 + lrow];
    const float mv1 = (float)mask[row0 + lrow + 64];

    // prologue: chunk 0 -> buffer 0
#pragma unroll
    for (int i = 0; i < 2; i++) {
        const int r = lrow + i * 64;
        const float mv = i ? mv1 : mv0;
        float4 a = *(const float4*)&X[(size_t)(row0 + r) * HDIM + lkq];
        As[0][r][lkq + 0] = f2tff(a.x * mv);
        As[0][r][lkq + 1] = f2tff(a.y * mv);
        As[0][r][lkq + 2] = f2tff(a.z * mv);
        As[0][r][lkq + 3] = f2tff(a.w * mv);
        float4 b = *(const float4*)&W[(size_t)r * HDIM + lkq];
        Bs[0][r][lkq + 0] = f2tff(b.x);
        Bs[0][r][lkq + 1] = f2tff(b.y);
        Bs[0][r][lkq + 2] = f2tff(b.z);
        Bs[0][r][lkq + 3] = f2tff(b.w);
    }
    __syncthreads();

    const int NC = HDIM / KC;   // 48
    float4 sa[2], sb[2];
    for (int c = 0; c < NC; c++) {
        const int cur = c & 1;
        if (c + 1 < NC) {
            const int k0 = (c + 1) * KC;
#pragma unroll
            for (int i = 0; i < 2; i++) {
                const int r = lrow + i * 64;
                sa[i] = *(const float4*)&X[(size_t)(row0 + r) * HDIM + k0 + lkq];
                sb[i] = *(const float4*)&W[(size_t)r * HDIM + k0 + lkq];
            }
        }
        const uint32_t aB = aBase + cur * bufB;
        const uint32_t bB = bBase + cur * bufB;
#pragma unroll
        for (int ks = 0; ks < 2; ks++) {
            const int k8 = ks * 8;
            uint32_t af[2][4], bf[8][2];
#pragma unroll
            for (int i = 0; i < 2; i++)
                ldsm4(af[i][0], af[i][1], af[i][2], af[i][3],
                      aB + (aOff[i] + k8) * 4);
#pragma unroll
            for (int jj = 0; jj < 4; jj++) {
                uint32_t r0, r1, r2, r3;
                ldsm4(r0, r1, r2, r3, bB + (bOff[jj] + k8) * 4);
                bf[2 * jj][0] = r0;  bf[2 * jj][1] = r1;
                bf[2 * jj + 1][0] = r2;  bf[2 * jj + 1][1] = r3;
            }
#pragma unroll
            for (int i = 0; i < 2; i++)
#pragma unroll
                for (int j = 0; j < 8; j++) mma8(acc[i][j], af[i], bf[j]);
        }
        if (c + 1 < NC) {
            const int nb = cur ^ 1;
#pragma unroll
            for (int i = 0; i < 2; i++) {
                const int r = lrow + i * 64;
                const float mv = i ? mv1 : mv0;
                As[nb][r][lkq + 0] = f2tff(sa[i].x * mv);
                As[nb][r][lkq + 1] = f2tff(sa[i].y * mv);
                As[nb][r][lkq + 2] = f2tff(sa[i].z * mv);
                As[nb][r][lkq + 3] = f2tff(sa[i].w * mv);
                Bs[nb][r][lkq + 0] = f2tff(sb[i].x);
                Bs[nb][r][lkq + 1] = f2tff(sb[i].y);
                Bs[nb][r][lkq + 2] = f2tff(sb[i].z);
                Bs[nb][r][lkq + 3] = f2tff(sb[i].w);
            }
        }
        __syncthreads();
    }

    // ---- fused L2 normalize ----
    float ssl[2], ssh[2];
#pragma unroll
    for (int i = 0; i < 2; i++) {
        float sl = 0.f, sh = 0.f;
#pragma unroll
        for (int j = 0; j < 8; j++) {
            sl += acc[i][j][0] * acc[i][j][0] + acc[i][j][1] * acc[i][j][1];
            sh += acc[i][j][2] * acc[i][j][2] + acc[i][j][3] * acc[i][j][3];
        }
        sl += __shfl_xor_sync(0xffffffffu, sl, 1);
        sl += __shfl_xor_sync(0xffffffffu, sl, 2);
        sh += __shfl_xor_sync(0xffffffffu, sh, 1);
        sh += __shfl_xor_sync(0xffffffffu, sh, 2);
        ssl[i] = sl; ssh[i] = sh;
        if (tig == 0) {
            ssb[wn][warpM + i * 16 + g]     = sl;
            ssb[wn][warpM + i * 16 + 8 + g] = sh;
        }
    }
    __syncthreads();
#pragma unroll
    for (int i = 0; i < 2; i++) {
        const int rl = warpM + i * 16 + g;
        const int rh = rl + 8;
        const float tl = ssb[0][rl] + ssb[1][rl];
        const float th = ssb[0][rh] + ssb[1][rh];
        const float scl = 1.f / fmaxf(sqrtf(tl), 1e-12f);
        const float sch = 1.f / fmaxf(sqrtf(th), 1e-12f);
#pragma unroll
        for (int j = 0; j < 8; j++) {
            float2 v;
            v.x = acc[i][j][0] * scl; v.y = acc[i][j][1] * scl;
            *(float2*)&E[(size_t)(row0 + rl) * DDIM + warpN + j * 8 + tig * 2] = v;
            v.x = acc[i][j][2] * sch; v.y = acc[i][j][3] * sch;
            *(float2*)&E[(size_t)(row0 + rh) * DDIM + warpN + j * 8 + tig * 2] = v;
        }
    }
}

// ---------------------------------------------------------------------------
// Kernel 2: per-batch similarity + partial max over a 128-doc chunk (tf32).
// Block (b, jc): sim tile [128 q x 128 docs], K = 128 (8 chunks of 16).
// ---------------------------------------------------------------------------
__global__ __launch_bounds__(256) void maxsim_tf32()
{
    __shared__ float As[2][128][LDK];
    __shared__ float Bs[2][128][LDK];
    __shared__ float mxb[2][128];

    const int b  = blockIdx.x;
    const int jc = blockIdx.y;
    const float* __restrict__ q = g_q_emb + (size_t)b * SQ * DDIM;
    const float* __restrict__ d = g_d_emb + ((size_t)b * SD + (size_t)jc * 128) * DDIM;

    const int tid  = threadIdx.x;
    const int lane = tid & 31;
    const int warp = tid >> 5;
    const int warpM = (warp & 3) * 32;
    const int warpN = (warp >> 2) * 64;
    const int wn = warp >> 2;
    const int g = lane >> 2, tig = lane & 3;
    const int l7 = lane & 7, b3 = (lane >> 3) & 1, b4 = (lane >> 4) & 1;

    const int lrow = tid >> 2;
    const int lkq  = (tid & 3) * 4;

    float acc[2][8][4];
#pragma unroll
    for (int i = 0; i < 2; i++)
#pragma unroll
        for (int j = 0; j < 8; j++)
#pragma unroll
            for (int e = 0; e < 4; e++) acc[i][j][e] = 0.f;

    uint32_t aOff[2], bOff[4];
#pragma unroll
    for (int i = 0; i < 2; i++)
        aOff[i] = (uint32_t)((warpM + i * 16 + l7 + b3 * 8) * LDK + b4 * 4);
#pragma unroll
    for (int jj = 0; jj < 4; jj++)
        bOff[jj] = (uint32_t)((warpN + jj * 16 + b4 * 8 + l7) * LDK + b3 * 4);

    const uint32_t aBase = s2u(&As[0][0][0]);
    const uint32_t bBase = s2u(&Bs[0][0][0]);
    const uint32_t bufB  = 128 * LDK * 4;

    // prologue chunk 0
#pragma unroll
    for (int i = 0; i < 2; i++) {
        const int r = lrow + i * 64;
        float4 a = *(const float4*)&q[(size_t)r * DDIM + lkq];
        As[0][r][lkq + 0] = f2tff(a.x); As[0][r][lkq + 1] = f2tff(a.y);
        As[0][r][lkq + 2] = f2tff(a.z); As[0][r][lkq + 3] = f2tff(a.w);
        float4 v = *(const float4*)&d[(size_t)r * DDIM + lkq];
        Bs[0][r][lkq + 0] = f2tff(v.x); Bs[0][r][lkq + 1] = f2tff(v.y);
        Bs[0][r][lkq + 2] = f2tff(v.z); Bs[0][r][lkq + 3] = f2tff(v.w);
    }
    __syncthreads();

    const int NC = DDIM / KC;   // 8
    float4 sa[2], sb[2];
    for (int c = 0; c < NC; c++) {
        const int cur = c & 1;
        if (c + 1 < NC) {
            const int k0 = (c + 1) * KC;
#pragma unroll
            for (int i = 0; i < 2; i++) {
                const int r = lrow + i * 64;
                sa[i] = *(const float4*)&q[(size_t)r * DDIM + k0 + lkq];
                sb[i] = *(const float4*)&d[(size_t)r * DDIM + k0 + lkq];
            }
        }
        const uint32_t aB = aBase + cur * bufB;
        const uint32_t bB = bBase + cur * bufB;
#pragma unroll
        for (int ks = 0; ks < 2; ks++) {
            const int k8 = ks * 8;
            uint32_t af[2][4], bf[8][2];
#pragma unroll
            for (int i = 0; i < 2; i++)
                ldsm4(af[i][0], af[i][1], af[i][2], af[i][3],
                      aB + (aOff[i] + k8) * 4);
#pragma unroll
            for (int jj = 0; jj < 4; jj++) {
                uint32_t r0, r1, r2, r3;
                ldsm4(r0, r1, r2, r3, bB + (bOff[jj] + k8) * 4);
                bf[2 * jj][0] = r0;  bf[2 * jj][1] = r1;
                bf[2 * jj + 1][0] = r2;  bf[2 * jj + 1][1] = r3;
            }
#pragma unroll
            for (int i = 0; i < 2; i++)
#pragma unroll
                for (int j = 0; j < 8; j++) mma8(acc[i][j], af[i], bf[j]);
        }
        if (c + 1 < NC) {
            const int nb = cur ^ 1;
#pragma unroll
            for (int i = 0; i < 2; i++) {
                const int r = lrow + i * 64;
                As[nb][r][lkq + 0] = f2tff(sa[i].x); As[nb][r][lkq + 1] = f2tff(sa[i].y);
                As[nb][r][lkq + 2] = f2tff(sa[i].z); As[nb][r][lkq + 3] = f2tff(sa[i].w);
                Bs[nb][r][lkq + 0] = f2tff(sb[i].x); Bs[nb][r][lkq + 1] = f2tff(sb[i].y);
                Bs[nb][r][lkq + 2] = f2tff(sb[i].z); Bs[nb][r][lkq + 3] = f2tff(sb[i].w);
            }
        }
        __syncthreads();
    }

    // ---- row max over this 128-doc chunk ----
#pragma unroll
    for (int i = 0; i < 2; i++) {
        float ml = acc[i][0][0], mh = acc[i][0][2];
#pragma unroll
        for (int j = 0; j < 8; j++) {
            ml = fmaxf(ml, fmaxf(acc[i][j][0], acc[i][j][1]));
            mh = fmaxf(mh, fmaxf(acc[i][j][2], acc[i][j][3]));
        }
        ml = fmaxf(ml, __shfl_xor_sync(0xffffffffu, ml, 1));
        ml = fmaxf(ml, __shfl_xor_sync(0xffffffffu, ml, 2));
        mh = fmaxf(mh, __shfl_xor_sync(0xffffffffu, mh, 1));
        mh = fmaxf(mh, __shfl_xor_sync(0xffffffffu, mh, 2));
        if (tig == 0) {
            mxb[wn][warpM + i * 16 + g]     = ml;
            mxb[wn][warpM + i * 16 + 8 + g] = mh;
        }
    }
    __syncthreads();
    if (tid < 128)
        g_pmax[((size_t)b * NJCHUNK + jc) * SQ + tid] = fmaxf(mxb[0][tid], mxb[1][tid]);
}

// ---------------------------------------------------------------------------
// Kernel 3: finalize. out[b] = sum_i max_jc pmax[b, jc, i]
// ---------------------------------------------------------------------------
__global__ __launch_bounds__(128) void finalize_kernel(float* __restrict__ out)
{
    const int b = blockIdx.x;
    const int i = threadIdx.x;
    float m = g_pmax[((size_t)b * NJCHUNK + 0) * SQ + i];
#pragma unroll
    for (int jc = 1; jc < NJCHUNK; jc++)
        m = fmaxf(m, g_pmax[((size_t)b * NJCHUNK + jc) * SQ + i]);
#pragma unroll
    for (int o = 16; o > 0; o >>= 1)
        m += __shfl_xor_sync(0xffffffffu, m, o, 32);
    __shared__ float s[4];
    if ((i & 31) == 0) s[i >> 5] = m;
    __syncthreads();
    if (i == 0) out[b] = s[0] + s[1] + s[2] + s[3];
}

// ---------------------------------------------------------------------------
extern "C" void kernel_launch(void* const* d_in, const int* in_sizes, int n_in,
                              void* d_out, int out_size)
{
    const float* qh = (const float*)d_in[0];   // [64,128,768]
    const int*   qm = (const int*)  d_in[1];   // [64,128]
    const float* dh = (const float*)d_in[2];   // [64,1024,768]
    const int*   dm = (const int*)  d_in[3];   // [64,1024]
    const float* W  = (const float*)d_in[4];   // [128,768]
    float* out = (float*)d_out;                // [64]

    float *gq = nullptr, *gd = nullptr;
    cudaGetSymbolAddress((void**)&gq, g_q_emb);
    cudaGetSymbolAddress((void**)&gd, g_d_emb);

    proj_tf32<<<NTOK_Q / 128, 256>>>(qh, qm, W, gq);
    proj_tf32<<<NTOK_D / 128, 256>>>(dh, dm, W, gd);
    maxsim_tf32<<<dim3(BATCH, NJCHUNK), 256>>>();
    finalize_kernel<<<BATCH, 128>>>(out);
}

// round 4
// speedup vs baseline: 3.6127x; 1.4787x over previous
#include <cuda_runtime.h>
#include <math.h>
#include <stdint.h>

// Problem constants
#define HDIM 768
#define DDIM 128
#define BATCH 64
#define SQ 128
#define SD 1024
#define NTOK_Q (BATCH * SQ)   // 8192
#define NTOK_D (BATCH * SD)   // 65536
#define NJCHUNK 8             // SD / 128
#define NBLK_Q (NTOK_Q / 128) // 64
#define NBLK_D (NTOK_D / 128) // 512

#define KC 16                 // K chunk (floats)
#define LDK 20                // smem row stride in words (5x16B -> conflict-free ldmatrix)
#define STAGE_WORDS (128 * LDK)          // per-side stage, words
#define STAGE_BYTES (STAGE_WORDS * 4)    // 10240
#define RING_OFF 1024
#define SMEM_BYTES (RING_OFF + 8 * STAGE_BYTES)   // 82944 (4 stages x 2 sides)

// Scratch (device globals: allocation-free per harness rules)
__device__ float g_q_emb[NTOK_Q * DDIM];            // 4 MB
__device__ float g_d_emb[(size_t)NTOK_D * DDIM];    // 32 MB
__device__ float g_pmax[BATCH * NJCHUNK * SQ];      // 256 KB

// ---------------------------------------------------------------------------
// helpers
// ---------------------------------------------------------------------------
__device__ __forceinline__ uint32_t s2u(const void* p) {
    return (uint32_t)__cvta_generic_to_shared(p);
}
__device__ __forceinline__ void cp16(uint32_t smem, const void* g) {
    asm volatile("cp.async.cg.shared.global [%0], [%1], 16;" :: "r"(smem), "l"(g));
}
#define CP_COMMIT() asm volatile("cp.async.commit_group;" ::: "memory")
#define CP_WAIT(n)  asm volatile("cp.async.wait_group %0;" :: "n"(n) : "memory")

__device__ __forceinline__ void ldsm4(uint32_t& r0, uint32_t& r1, uint32_t& r2,
                                      uint32_t& r3, uint32_t addr) {
    asm volatile("ldmatrix.sync.aligned.m8n8.x4.shared.b16 {%0,%1,%2,%3}, [%4];"
                 : "=r"(r0), "=r"(r1), "=r"(r2), "=r"(r3) : "r"(addr));
}
__device__ __forceinline__ void mma8(float c[4], const uint32_t a[4], const uint32_t b[2]) {
    asm volatile("mma.sync.aligned.m16n8k8.row.col.f32.tf32.tf32.f32 "
                 "{%0,%1,%2,%3}, {%4,%5,%6,%7}, {%8,%9}, {%0,%1,%2,%3};"
                 : "+f"(c[0]), "+f"(c[1]), "+f"(c[2]), "+f"(c[3])
                 : "r"(a[0]), "r"(a[1]), "r"(a[2]), "r"(a[3]),
                   "r"(b[0]), "r"(b[1]));
}

// Load one KC=16 chunk of A and B tiles into ring stage st via cp.async.
// 128 rows x 16 floats per side = 512 x 16B; 2 cp16 per thread per side.
__device__ __forceinline__ void load_stage(uint32_t sbase, int st,
                                           const float* gA, const float* gB,
                                           int strideA, int tid)
{
    const uint32_t smA = sbase + RING_OFF + (uint32_t)st * STAGE_BYTES;
    const uint32_t smB = sbase + RING_OFF + 4 * STAGE_BYTES + (uint32_t)st * STAGE_BYTES;
#pragma unroll
    for (int i = 0; i < 2; i++) {
        int idx = tid + i * 256;        // [0,512)
        int r = idx >> 2;               // [0,128)
        int kq = (idx & 3) * 4;         // {0,4,8,12}
        uint32_t off = (uint32_t)(r * LDK + kq) * 4;
        cp16(smA + off, gA + (size_t)r * strideA + kq);
        cp16(smB + off, gB + (size_t)r * HDIM + kq);   // B is W (stride HDIM) or emb (DDIM) -- see wrappers
    }
}
// variant with explicit B stride
__device__ __forceinline__ void load_stage2(uint32_t sbase, int st,
                                            const float* gA, const float* gB,
                                            int strideA, int strideB, int tid)
{
    const uint32_t smA = sbase + RING_OFF + (uint32_t)st * STAGE_BYTES;
    const uint32_t smB = sbase + RING_OFF + 4 * STAGE_BYTES + (uint32_t)st * STAGE_BYTES;
#pragma unroll
    for (int i = 0; i < 2; i++) {
        int idx = tid + i * 256;
        int r = idx >> 2;
        int kq = (idx & 3) * 4;
        uint32_t off = (uint32_t)(r * LDK + kq) * 4;
        cp16(smA + off, gA + (size_t)r * strideA + kq);
        cp16(smB + off, gB + (size_t)r * strideB + kq);
    }
}

// Consume one KC=16 stage: 2 x (ldmatrix + 16 mma) per warp.
__device__ __forceinline__ void consume_stage(uint32_t sbase, int st,
                                              const uint32_t aOff[2],
                                              const uint32_t bOff[4],
                                              float acc[2][8][4])
{
    const uint32_t aB = sbase + RING_OFF + (uint32_t)st * STAGE_BYTES;
    const uint32_t bB = sbase + RING_OFF + 4 * STAGE_BYTES + (uint32_t)st * STAGE_BYTES;
#pragma unroll
    for (int ks = 0; ks < 2; ks++) {
        const int k8 = ks * 8;
        uint32_t af[2][4], bf[8][2];
#pragma unroll
        for (int i = 0; i < 2; i++)
            ldsm4(af[i][0], af[i][1], af[i][2], af[i][3], aB + (aOff[i] + k8) * 4);
#pragma unroll
        for (int jj = 0; jj < 4; jj++) {
            uint32_t r0, r1, r2, r3;
            ldsm4(r0, r1, r2, r3, bB + (bOff[jj] + k8) * 4);
            bf[2 * jj][0] = r0;  bf[2 * jj][1] = r1;
            bf[2 * jj + 1][0] = r2;  bf[2 * jj + 1][1] = r3;
        }
#pragma unroll
        for (int i = 0; i < 2; i++)
#pragma unroll
            for (int j = 0; j < 8; j++) mma8(acc[i][j], af[i], bf[j]);
    }
}

__device__ __forceinline__ void frag_offsets(int warp, int lane,
                                             uint32_t aOff[2], uint32_t bOff[4],
                                             int& warpM, int& warpN)
{
    warpM = (warp & 3) * 32;
    warpN = (warp >> 2) * 64;
    const int l7 = lane & 7, b3 = (lane >> 3) & 1, b4 = (lane >> 4) & 1;
#pragma unroll
    for (int i = 0; i < 2; i++)
        aOff[i] = (uint32_t)((warpM + i * 16 + l7 + b3 * 8) * LDK + b4 * 4);
#pragma unroll
    for (int jj = 0; jj < 4; jj++)
        bOff[jj] = (uint32_t)((warpN + jj * 16 + b4 * 8 + l7) * LDK + b3 * 4);
}

// ---------------------------------------------------------------------------
// Kernel 1: projection + L2 normalize (tf32 mma.sync, cp.async 4-stage ring).
// Unified grid: blocks [0,64) -> query tokens, [64,576) -> doc tokens.
// Mask folded into epilogue scale (mask commutes with the projection).
// ---------------------------------------------------------------------------
__global__ __launch_bounds__(256) void proj_tc(
    const float* __restrict__ Xq, const int* __restrict__ Mq,
    const float* __restrict__ Xd, const int* __restrict__ Md,
    const float* __restrict__ W,
    float* __restrict__ Eq, float* __restrict__ Ed)
{
    extern __shared__ char smem[];
    const uint32_t sbase = s2u(smem);
    const int tid  = threadIdx.x;
    const int lane = tid & 31;
    const int warp = tid >> 5;

    const bool isQ = blockIdx.x < NBLK_Q;
    const int  rb  = isQ ? blockIdx.x : (blockIdx.x - NBLK_Q);
    const int  row0 = rb * 128;
    const float* X = isQ ? Xq : Xd;
    const int*   M = isQ ? Mq : Md;
    float*       E = isQ ? Eq : Ed;
    const float* gA = X + (size_t)row0 * HDIM;

    uint32_t aOff[2], bOff[4];
    int warpM, warpN;
    frag_offsets(warp, lane, aOff, bOff, warpM, warpN);
    const int wn = warp >> 2;
    const int g = lane >> 2, tig = lane & 3;

    float acc[2][8][4];
#pragma unroll
    for (int i = 0; i < 2; i++)
#pragma unroll
        for (int j = 0; j < 8; j++)
#pragma unroll
            for (int e = 0; e < 4; e++) acc[i][j][e] = 0.f;

    // prologue: stages 0..2
#pragma unroll
    for (int s = 0; s < 3; s++) {
        load_stage2(sbase, s, gA + s * KC, W + s * KC, HDIM, HDIM, tid);
        CP_COMMIT();
    }

    const int NC = HDIM / KC;   // 48
    for (int k = 0; k < NC; k++) {
        CP_WAIT(2);
        __syncthreads();
        const int m = k + 3;
        if (m < NC) {
            load_stage2(sbase, m & 3, gA + m * KC, W + m * KC, HDIM, HDIM, tid);
            CP_COMMIT();
        }
        consume_stage(sbase, k & 3, aOff, bOff, acc);
    }
    __syncthreads();   // smem reads done; reuse ring for reductions

    // ---- fused L2 normalize (mask folded into scale) ----
    float* ssb = (float*)(smem + RING_OFF);   // [2][128]
#pragma unroll
    for (int i = 0; i < 2; i++) {
        float sl = 0.f, sh = 0.f;
#pragma unroll
        for (int j = 0; j < 8; j++) {
            sl += acc[i][j][0] * acc[i][j][0] + acc[i][j][1] * acc[i][j][1];
            sh += acc[i][j][2] * acc[i][j][2] + acc[i][j][3] * acc[i][j][3];
        }
        sl += __shfl_xor_sync(0xffffffffu, sl, 1);
        sl += __shfl_xor_sync(0xffffffffu, sl, 2);
        sh += __shfl_xor_sync(0xffffffffu, sh, 1);
        sh += __shfl_xor_sync(0xffffffffu, sh, 2);
        if (tig == 0) {
            ssb[wn * 128 + warpM + i * 16 + g]     = sl;
            ssb[wn * 128 + warpM + i * 16 + 8 + g] = sh;
        }
    }
    __syncthreads();
#pragma unroll
    for (int i = 0; i < 2; i++) {
        const int rl = warpM + i * 16 + g;
        const int rh = rl + 8;
        const float tl = ssb[rl] + ssb[128 + rl];
        const float th = ssb[rh] + ssb[128 + rh];
        const float mvl = (float)M[row0 + rl];
        const float mvh = (float)M[row0 + rh];
        const float scl = mvl / fmaxf(sqrtf(tl), 1e-12f);
        const float sch = mvh / fmaxf(sqrtf(th), 1e-12f);
#pragma unroll
        for (int j = 0; j < 8; j++) {
            float2 v;
            v.x = acc[i][j][0] * scl; v.y = acc[i][j][1] * scl;
            *(float2*)&E[(size_t)(row0 + rl) * DDIM + warpN + j * 8 + tig * 2] = v;
            v.x = acc[i][j][2] * sch; v.y = acc[i][j][3] * sch;
            *(float2*)&E[(size_t)(row0 + rh) * DDIM + warpN + j * 8 + tig * 2] = v;
        }
    }
}

// ---------------------------------------------------------------------------
// Kernel 2: per-batch similarity + partial max (tf32 mma.sync, cp.async ring).
// Block (b, jc): [128 q x 128 docs], K = 128 (8 chunks of 16).
// ---------------------------------------------------------------------------
__global__ __launch_bounds__(256) void maxsim_tc()
{
    extern __shared__ char smem[];
    const uint32_t sbase = s2u(smem);
    const int tid  = threadIdx.x;
    const int lane = tid & 31;
    const int warp = tid >> 5;
    const int b  = blockIdx.x;
    const int jc = blockIdx.y;

    const float* q = g_q_emb + (size_t)b * SQ * DDIM;
    const float* d = g_d_emb + ((size_t)b * SD + (size_t)jc * 128) * DDIM;

    uint32_t aOff[2], bOff[4];
    int warpM, warpN;
    frag_offsets(warp, lane, aOff, bOff, warpM, warpN);
    const int wn = warp >> 2;
    const int g = lane >> 2, tig = lane & 3;

    float acc[2][8][4];
#pragma unroll
    for (int i = 0; i < 2; i++)
#pragma unroll
        for (int j = 0; j < 8; j++)
#pragma unroll
            for (int e = 0; e < 4; e++) acc[i][j][e] = 0.f;

#pragma unroll
    for (int s = 0; s < 3; s++) {
        load_stage2(sbase, s, q + s * KC, d + s * KC, DDIM, DDIM, tid);
        CP_COMMIT();
    }

    const int NC = DDIM / KC;   // 8
    for (int k = 0; k < NC; k++) {
        CP_WAIT(2);
        __syncthreads();
        const int m = k + 3;
        if (m < NC) {
            load_stage2(sbase, m & 3, q + m * KC, d + m * KC, DDIM, DDIM, tid);
            CP_COMMIT();
        }
        consume_stage(sbase, k & 3, aOff, bOff, acc);
    }
    __syncthreads();

    // ---- row max over this 128-doc chunk ----
    float* mxb = (float*)(smem + RING_OFF);   // [2][128]
#pragma unroll
    for (int i = 0; i < 2; i++) {
        float ml = acc[i][0][0], mh = acc[i][0][2];
#pragma unroll
        for (int j = 0; j < 8; j++) {
            ml = fmaxf(ml, fmaxf(acc[i][j][0], acc[i][j][1]));
            mh = fmaxf(mh, fmaxf(acc[i][j][2], acc[i][j][3]));
        }
        ml = fmaxf(ml, __shfl_xor_sync(0xffffffffu, ml, 1));
        ml = fmaxf(ml, __shfl_xor_sync(0xffffffffu, ml, 2));
        mh = fmaxf(mh, __shfl_xor_sync(0xffffffffu, mh, 1));
        mh = fmaxf(mh, __shfl_xor_sync(0xffffffffu, mh, 2));
        if (tig == 0) {
            mxb[wn * 128 + warpM + i * 16 + g]     = ml;
            mxb[wn * 128 + warpM + i * 16 + 8 + g] = mh;
        }
    }
    __syncthreads();
    if (tid < 128)
        g_pmax[((size_t)b * NJCHUNK + jc) * SQ + tid] =
            fmaxf(mxb[tid], mxb[128 + tid]);
}

// ---------------------------------------------------------------------------
// Kernel 3: finalize. out[b] = sum_i max_jc pmax[b, jc, i]
// ---------------------------------------------------------------------------
__global__ __launch_bounds__(128) void finalize_kernel(float* __restrict__ out)
{
    const int b = blockIdx.x;
    const int i = threadIdx.x;
    float m = g_pmax[((size_t)b * NJCHUNK + 0) * SQ + i];
#pragma unroll
    for (int jc = 1; jc < NJCHUNK; jc++)
        m = fmaxf(m, g_pmax[((size_t)b * NJCHUNK + jc) * SQ + i]);
#pragma unroll
    for (int o = 16; o > 0; o >>= 1)
        m += __shfl_xor_sync(0xffffffffu, m, o, 32);
    __shared__ float s[4];
    if ((i & 31) == 0) s[i >> 5] = m;
    __syncthreads();
    if (i == 0) out[b] = s[0] + s[1] + s[2] + s[3];
}

// ---------------------------------------------------------------------------
extern "C" void kernel_launch(void* const* d_in, const int* in_sizes, int n_in,
                              void* d_out, int out_size)
{
    const float* qh = (const float*)d_in[0];   // [64,128,768]
    const int*   qm = (const int*)  d_in[1];   // [64,128]
    const float* dh = (const float*)d_in[2];   // [64,1024,768]
    const int*   dm = (const int*)  d_in[3];   // [64,1024]
    const float* W  = (const float*)d_in[4];   // [128,768]
    float* out = (float*)d_out;                // [64]

    float *gq = nullptr, *gd = nullptr;
    cudaGetSymbolAddress((void**)&gq, g_q_emb);
    cudaGetSymbolAddress((void**)&gd, g_d_emb);

    cudaFuncSetAttribute(proj_tc, cudaFuncAttributeMaxDynamicSharedMemorySize, SMEM_BYTES);
    cudaFuncSetAttribute(maxsim_tc, cudaFuncAttributeMaxDynamicSharedMemorySize, SMEM_BYTES);

    proj_tc<<<NBLK_Q + NBLK_D, 256, SMEM_BYTES>>>(qh, qm, dh, dm, W, gq, gd);
    maxsim_tc<<<dim3(BATCH, NJCHUNK), 256, SMEM_BYTES>>>();
    finalize_kernel<<<BATCH, 128>>>(out);
}

// round 5
// speedup vs baseline: 4.1543x; 1.1499x over previous
#include <cuda_runtime.h>
#include <math.h>
#include <stdint.h>

// Problem constants
#define HDIM 768
#define DDIM 128
#define BATCH 64
#define SQ 128
#define SD 1024
#define NTOK_Q (BATCH * SQ)   // 8192
#define NTOK_D (BATCH * SD)   // 65536
#define NJCHUNK 8             // SD / 128
#define NBLK_Q (NTOK_Q / 128) // 64
#define NBLK_D (NTOK_D / 128) // 512

#define KC 32                 // K chunk (floats)
#define LDK 36                // smem row stride in words (9x16B, odd -> conflict-free ldmatrix)
#define NSTAGE 3
#define STAGE_BYTES (128 * LDK * 4)      // 18432
#define RING_OFF 1024
#define SMEM_BYTES (RING_OFF + 2 * NSTAGE * STAGE_BYTES)   // 111616

// Scratch (device globals: allocation-free per harness rules)
__device__ float g_q_emb[NTOK_Q * DDIM];            // 4 MB
__device__ float g_d_emb[(size_t)NTOK_D * DDIM];    // 32 MB
__device__ float g_pmax[BATCH * NJCHUNK * SQ];      // 256 KB
__device__ float g_w_rna[DDIM * HDIM];              // 384 KB (tf32-rounded W)

// ---------------------------------------------------------------------------
// helpers
// ---------------------------------------------------------------------------
__device__ __forceinline__ uint32_t s2u(const void* p) {
    return (uint32_t)__cvta_generic_to_shared(p);
}
__device__ __forceinline__ float f2tff(float x) {
    uint32_t u; asm("cvt.rna.tf32.f32 %0, %1;" : "=r"(u) : "f"(x));
    return __uint_as_float(u);
}
__device__ __forceinline__ void cp16(uint32_t smem, const void* g) {
    asm volatile("cp.async.cg.shared.global [%0], [%1], 16;" :: "r"(smem), "l"(g));
}
#define CP_COMMIT() asm volatile("cp.async.commit_group;" ::: "memory")
#define CP_WAIT(n)  asm volatile("cp.async.wait_group %0;" :: "n"(n) : "memory")

__device__ __forceinline__ void ldsm4(uint32_t& r0, uint32_t& r1, uint32_t& r2,
                                      uint32_t& r3, uint32_t addr) {
    asm volatile("ldmatrix.sync.aligned.m8n8.x4.shared.b16 {%0,%1,%2,%3}, [%4];"
                 : "=r"(r0), "=r"(r1), "=r"(r2), "=r"(r3) : "r"(addr));
}
__device__ __forceinline__ void mma8(float c[4], const uint32_t a[4], const uint32_t b[2]) {
    asm volatile("mma.sync.aligned.m16n8k8.row.col.f32.tf32.tf32.f32 "
                 "{%0,%1,%2,%3}, {%4,%5,%6,%7}, {%8,%9}, {%0,%1,%2,%3};"
                 : "+f"(c[0]), "+f"(c[1]), "+f"(c[2]), "+f"(c[3])
                 : "r"(a[0]), "r"(a[1]), "r"(a[2]), "r"(a[3]),
                   "r"(b[0]), "r"(b[1]));
}

// Load one KC=32 chunk of A and B tiles into ring stage st via cp.async.
// 128 rows x 32 floats per side = 1024 x 16B; 4 cp16 per thread per side.
__device__ __forceinline__ void load_stage(uint32_t sbase, int st,
                                           const float* gA, const float* gB,
                                           int strideA, int strideB, int tid)
{
    const uint32_t smA = sbase + RING_OFF + (uint32_t)st * STAGE_BYTES;
    const uint32_t smB = smA + NSTAGE * STAGE_BYTES;
#pragma unroll
    for (int i = 0; i < 4; i++) {
        int idx = tid + i * 256;        // [0,1024)
        int r = idx >> 3;               // [0,128)
        int kq = (idx & 7) * 4;         // {0,4,...,28}
        uint32_t off = (uint32_t)(r * LDK + kq) * 4;
        cp16(smA + off, gA + (size_t)r * strideA + kq);
        cp16(smB + off, gB + (size_t)r * strideB + kq);
    }
}

// Consume one KC=32 stage: 4 k8 steps, each 6 ldmatrix.x4 + 16 mma per warp.
__device__ __forceinline__ void consume_stage(uint32_t sbase, int st,
                                              const uint32_t aOff[2],
                                              const uint32_t bOff[4],
                                              float acc[2][8][4])
{
    const uint32_t aB = sbase + RING_OFF + (uint32_t)st * STAGE_BYTES;
    const uint32_t bB = aB + NSTAGE * STAGE_BYTES;
#pragma unroll
    for (int ks = 0; ks < 4; ks++) {
        const int k8 = ks * 8;
        uint32_t af[2][4], bf[8][2];
#pragma unroll
        for (int i = 0; i < 2; i++)
            ldsm4(af[i][0], af[i][1], af[i][2], af[i][3], aB + (aOff[i] + k8) * 4);
#pragma unroll
        for (int jj = 0; jj < 4; jj++) {
            uint32_t r0, r1, r2, r3;
            ldsm4(r0, r1, r2, r3, bB + (bOff[jj] + k8) * 4);
            bf[2 * jj][0] = r0;  bf[2 * jj][1] = r1;
            bf[2 * jj + 1][0] = r2;  bf[2 * jj + 1][1] = r3;
        }
#pragma unroll
        for (int i = 0; i < 2; i++)
#pragma unroll
            for (int j = 0; j < 8; j++) mma8(acc[i][j], af[i], bf[j]);
    }
}

__device__ __forceinline__ void frag_offsets(int warp, int lane,
                                             uint32_t aOff[2], uint32_t bOff[4],
                                             int& warpM, int& warpN)
{
    warpM = (warp & 3) * 32;
    warpN = (warp >> 2) * 64;
    const int l7 = lane & 7, b3 = (lane >> 3) & 1, b4 = (lane >> 4) & 1;
#pragma unroll
    for (int i = 0; i < 2; i++)
        aOff[i] = (uint32_t)((warpM + i * 16 + l7 + b3 * 8) * LDK + b4 * 4);
#pragma unroll
    for (int jj = 0; jj < 4; jj++)
        bOff[jj] = (uint32_t)((warpN + jj * 16 + b4 * 8 + l7) * LDK + b3 * 4);
}

// ---------------------------------------------------------------------------
// Kernel 0: tf32-round W once (makes the W operand exact under in-MMA RZ).
// ---------------------------------------------------------------------------
__global__ __launch_bounds__(256) void round_w(const float* __restrict__ W)
{
    int i = blockIdx.x * 256 + threadIdx.x;     // float4 index
    float4 v = ((const float4*)W)[i];
    v.x = f2tff(v.x); v.y = f2tff(v.y); v.z = f2tff(v.z); v.w = f2tff(v.w);
    ((float4*)g_w_rna)[i] = v;
}

// ---------------------------------------------------------------------------
// Kernel 1: projection + L2 normalize (tf32 mma.sync, 3-stage KC=32 ring).
// Unified grid: blocks [0,64) -> query tokens, [64,576) -> doc tokens.
// Mask folded into epilogue scale; embeddings written tf32-rounded so the
// maxsim MMA consumes exactly-representable operands.
// ---------------------------------------------------------------------------
__global__ __launch_bounds__(256, 2) void proj_tc(
    const float* __restrict__ Xq, const int* __restrict__ Mq,
    const float* __restrict__ Xd, const int* __restrict__ Md,
    float* __restrict__ Eq, float* __restrict__ Ed)
{
    extern __shared__ char smem[];
    const uint32_t sbase = s2u(smem);
    const int tid  = threadIdx.x;
    const int lane = tid & 31;
    const int warp = tid >> 5;

    const bool isQ = blockIdx.x < NBLK_Q;
    const int  rb  = isQ ? blockIdx.x : (blockIdx.x - NBLK_Q);
    const int  row0 = rb * 128;
    const float* X = isQ ? Xq : Xd;
    const int*   M = isQ ? Mq : Md;
    float*       E = isQ ? Eq : Ed;
    const float* gA = X + (size_t)row0 * HDIM;
    const float* gB = g_w_rna;

    uint32_t aOff[2], bOff[4];
    int warpM, warpN;
    frag_offsets(warp, lane, aOff, bOff, warpM, warpN);
    const int wn = warp >> 2;
    const int g = lane >> 2, tig = lane & 3;

    float acc[2][8][4];
#pragma unroll
    for (int i = 0; i < 2; i++)
#pragma unroll
        for (int j = 0; j < 8; j++)
#pragma unroll
            for (int e = 0; e < 4; e++) acc[i][j][e] = 0.f;

    // prologue: stages 0,1
#pragma unroll
    for (int s = 0; s < 2; s++) {
        load_stage(sbase, s, gA + s * KC, gB + s * KC, HDIM, HDIM, tid);
        CP_COMMIT();
    }

    const int NC = HDIM / KC;   // 24
    int st = 0, stn = 2;        // consume stage, next-load stage
    for (int k = 0; k < NC; k++) {
        CP_WAIT(1);
        __syncthreads();
        const int m = k + 2;
        if (m < NC) {
            load_stage(sbase, stn, gA + m * KC, gB + m * KC, HDIM, HDIM, tid);
            CP_COMMIT();
        }
        consume_stage(sbase, st, aOff, bOff, acc);
        st = (st + 1 == NSTAGE) ? 0 : st + 1;
        stn = (stn + 1 == NSTAGE) ? 0 : stn + 1;
    }
    __syncthreads();   // smem reads done; reuse ring for reductions

    // ---- fused L2 normalize (mask folded into scale) ----
    float* ssb = (float*)(smem + RING_OFF);   // [2][128]
#pragma unroll
    for (int i = 0; i < 2; i++) {
        float sl = 0.f, sh = 0.f;
#pragma unroll
        for (int j = 0; j < 8; j++) {
            sl += acc[i][j][0] * acc[i][j][0] + acc[i][j][1] * acc[i][j][1];
            sh += acc[i][j][2] * acc[i][j][2] + acc[i][j][3] * acc[i][j][3];
        }
        sl += __shfl_xor_sync(0xffffffffu, sl, 1);
        sl += __shfl_xor_sync(0xffffffffu, sl, 2);
        sh += __shfl_xor_sync(0xffffffffu, sh, 1);
        sh += __shfl_xor_sync(0xffffffffu, sh, 2);
        if (tig == 0) {
            ssb[wn * 128 + warpM + i * 16 + g]     = sl;
            ssb[wn * 128 + warpM + i * 16 + 8 + g] = sh;
        }
    }
    __syncthreads();
#pragma unroll
    for (int i = 0; i < 2; i++) {
        const int rl = warpM + i * 16 + g;
        const int rh = rl + 8;
        const float tl = ssb[rl] + ssb[128 + rl];
        const float th = ssb[rh] + ssb[128 + rh];
        const float mvl = (float)M[row0 + rl];
        const float mvh = (float)M[row0 + rh];
        const float scl = mvl / fmaxf(sqrtf(tl), 1e-12f);
        const float sch = mvh / fmaxf(sqrtf(th), 1e-12f);
#pragma unroll
        for (int j = 0; j < 8; j++) {
            float2 v;
            v.x = f2tff(acc[i][j][0] * scl); v.y = f2tff(acc[i][j][1] * scl);
            *(float2*)&E[(size_t)(row0 + rl) * DDIM + warpN + j * 8 + tig * 2] = v;
            v.x = f2tff(acc[i][j][2] * sch); v.y = f2tff(acc[i][j][3] * sch);
            *(float2*)&E[(size_t)(row0 + rh) * DDIM + warpN + j * 8 + tig * 2] = v;
        }
    }
}

// ---------------------------------------------------------------------------
// Kernel 2: per-batch similarity + partial max (tf32 mma.sync, KC=32 ring).
// Block (b, jc): [128 q x 128 docs], K = 128 (4 chunks of 32).
// ---------------------------------------------------------------------------
__global__ __launch_bounds__(256, 2) void maxsim_tc()
{
    extern __shared__ char smem[];
    const uint32_t sbase = s2u(smem);
    const int tid  = threadIdx.x;
    const int lane = tid & 31;
    const int warp = tid >> 5;
    const int b  = blockIdx.x;
    const int jc = blockIdx.y;

    const float* q = g_q_emb + (size_t)b * SQ * DDIM;
    const float* d = g_d_emb + ((size_t)b * SD + (size_t)jc * 128) * DDIM;

    uint32_t aOff[2], bOff[4];
    int warpM, warpN;
    frag_offsets(warp, lane, aOff, bOff, warpM, warpN);
    const int wn = warp >> 2;
    const int g = lane >> 2, tig = lane & 3;

    float acc[2][8][4];
#pragma unroll
    for (int i = 0; i < 2; i++)
#pragma unroll
        for (int j = 0; j < 8; j++)
#pragma unroll
            for (int e = 0; e < 4; e++) acc[i][j][e] = 0.f;

#pragma unroll
    for (int s = 0; s < 2; s++) {
        load_stage(sbase, s, q + s * KC, d + s * KC, DDIM, DDIM, tid);
        CP_COMMIT();
    }

    const int NC = DDIM / KC;   // 4
    int st = 0, stn = 2;
    for (int k = 0; k < NC; k++) {
        CP_WAIT(1);
        __syncthreads();
        const int m = k + 2;
        if (m < NC) {
            load_stage(sbase, stn, q + m * KC, d + m * KC, DDIM, DDIM, tid);
            CP_COMMIT();
        }
        consume_stage(sbase, st, aOff, bOff, acc);
        st = (st + 1 == NSTAGE) ? 0 : st + 1;
        stn = (stn + 1 == NSTAGE) ? 0 : stn + 1;
    }
    __syncthreads();

    // ---- row max over this 128-doc chunk ----
    float* mxb = (float*)(smem + RING_OFF);   // [2][128]
#pragma unroll
    for (int i = 0; i < 2; i++) {
        float ml = acc[i][0][0], mh = acc[i][0][2];
#pragma unroll
        for (int j = 0; j < 8; j++) {
            ml = fmaxf(ml, fmaxf(acc[i][j][0], acc[i][j][1]));
            mh = fmaxf(mh, fmaxf(acc[i][j][2], acc[i][j][3]));
        }
        ml = fmaxf(ml, __shfl_xor_sync(0xffffffffu, ml, 1));
        ml = fmaxf(ml, __shfl_xor_sync(0xffffffffu, ml, 2));
        mh = fmaxf(mh, __shfl_xor_sync(0xffffffffu, mh, 1));
        mh = fmaxf(mh, __shfl_xor_sync(0xffffffffu, mh, 2));
        if (tig == 0) {
            mxb[wn * 128 + warpM + i * 16 + g]     = ml;
            mxb[wn * 128 + warpM + i * 16 + 8 + g] = mh;
        }
    }
    __syncthreads();
    if (tid < 128)
        g_pmax[((size_t)b * NJCHUNK + jc) * SQ + tid] =
            fmaxf(mxb[tid], mxb[128 + tid]);
}

// ---------------------------------------------------------------------------
// Kernel 3: finalize. out[b] = sum_i max_jc pmax[b, jc, i]
// ---------------------------------------------------------------------------
__global__ __launch_bounds__(128) void finalize_kernel(float* __restrict__ out)
{
    const int b = blockIdx.x;
    const int i = threadIdx.x;
    float m = g_pmax[((size_t)b * NJCHUNK + 0) * SQ + i];
#pragma unroll
    for (int jc = 1; jc < NJCHUNK; jc++)
        m = fmaxf(m, g_pmax[((size_t)b * NJCHUNK + jc) * SQ + i]);
#pragma unroll
    for (int o = 16; o > 0; o >>= 1)
        m += __shfl_xor_sync(0xffffffffu, m, o, 32);
    __shared__ float s[4];
    if ((i & 31) == 0) s[i >> 5] = m;
    __syncthreads();
    if (i == 0) out[b] = s[0] + s[1] + s[2] + s[3];
}

// ---------------------------------------------------------------------------
extern "C" void kernel_launch(void* const* d_in, const int* in_sizes, int n_in,
                              void* d_out, int out_size)
{
    const float* qh = (const float*)d_in[0];   // [64,128,768]
    const int*   qm = (const int*)  d_in[1];   // [64,128]
    const float* dh = (const float*)d_in[2];   // [64,1024,768]
    const int*   dm = (const int*)  d_in[3];   // [64,1024]
    const float* W  = (const float*)d_in[4];   // [128,768]
    float* out = (float*)d_out;                // [64]

    float *gq = nullptr, *gd = nullptr;
    cudaGetSymbolAddress((void**)&gq, g_q_emb);
    cudaGetSymbolAddress((void**)&gd, g_d_emb);

    cudaFuncSetAttribute(proj_tc, cudaFuncAttributeMaxDynamicSharedMemorySize, SMEM_BYTES);
    cudaFuncSetAttribute(maxsim_tc, cudaFuncAttributeMaxDynamicSharedMemorySize, SMEM_BYTES);

    round_w<<<(DDIM * HDIM / 4) / 256, 256>>>(W);
    proj_tc<<<NBLK_Q + NBLK_D, 256, SMEM_BYTES>>>(qh, qm, dh, dm, gq, gd);
    maxsim_tc<<<dim3(BATCH, NJCHUNK), 256, SMEM_BYTES>>>();
    finalize_kernel<<<BATCH, 128>>>(out);
}